// round 16
// baseline (speedup 1.0000x reference)
#include <cuda_runtime.h>
#include <cuda_fp16.h>
#include <cstdint>

// Problem constants
#define BATCH   16
#define TLEN    4096
#define KW      15

// Tiling
#define TT      256      // time tile per CTA
#define NTHREADS 256     // 8 warps; each warp: 2 m16 tiles (32 t)
#define TROWS   272      // staged t' rows: [t0-8, t0+TT+8)
#define NTQ     68       // t-quads
#define SBB     48       // bytes per xT row (fits CINP<=24 fp16, conflict-free)
#define SBW     12       // words per xT row

// ---------------------------------------------------------------------------
// Intermediate activation buffers (static device globals; no runtime alloc)
// ---------------------------------------------------------------------------
__device__ float g_h1[(size_t)BATCH * 512 * TLEN];
__device__ float g_h2[(size_t)BATCH * 256 * TLEN];
__device__ float g_h3[(size_t)BATCH * 256 * TLEN];
__device__ float g_h4[(size_t)BATCH * 128 * TLEN];
__device__ float g_h5[(size_t)BATCH *  64 * TLEN];
__device__ float g_h6[(size_t)BATCH *  32 * TLEN];
__device__ float g_h7[(size_t)BATCH *  16 * TLEN];

// ---------------------------------------------------------------------------
// fp16 / mma / ldmatrix helpers
// ---------------------------------------------------------------------------
__device__ __forceinline__ uint32_t packh2(float a, float b) {
    __half2 h = __floats2half2_rn(a, b);          // a -> low half
    return *reinterpret_cast<uint32_t*>(&h);
}
__device__ __forceinline__ void mma_f16_k16(float* d,
        uint32_t a0, uint32_t a1, uint32_t a2, uint32_t a3,
        uint32_t b0, uint32_t b1) {
    asm("mma.sync.aligned.m16n8k16.row.col.f32.f16.f16.f32 "
        "{%0,%1,%2,%3}, {%4,%5,%6,%7}, {%8,%9}, {%0,%1,%2,%3};"
        : "+f"(d[0]), "+f"(d[1]), "+f"(d[2]), "+f"(d[3])
        : "r"(a0), "r"(a1), "r"(a2), "r"(a3), "r"(b0), "r"(b1));
}
__device__ __forceinline__ void mma_f16_k8(float* d,
        uint32_t a0, uint32_t a1, uint32_t b0) {
    asm("mma.sync.aligned.m16n8k8.row.col.f32.f16.f16.f32 "
        "{%0,%1,%2,%3}, {%4,%5}, {%6}, {%0,%1,%2,%3};"
        : "+f"(d[0]), "+f"(d[1]), "+f"(d[2]), "+f"(d[3])
        : "r"(a0), "r"(a1), "r"(b0));
}
__device__ __forceinline__ void ldsm_x4(uint32_t& r0, uint32_t& r1,
                                        uint32_t& r2, uint32_t& r3, uint32_t addr) {
    asm volatile("ldmatrix.sync.aligned.m8n8.x4.shared.b16 {%0,%1,%2,%3}, [%4];"
                 : "=r"(r0), "=r"(r1), "=r"(r2), "=r"(r3) : "r"(addr));
}
__device__ __forceinline__ void ldsm_x2(uint32_t& r0, uint32_t& r1, uint32_t addr) {
    asm volatile("ldmatrix.sync.aligned.m8n8.x2.shared.b16 {%0,%1}, [%2];"
                 : "=r"(r0), "=r"(r1) : "r"(addr));
}

// ---------------------------------------------------------------------------
// Grouped conv1d K=15 SAME via fp16 split-precision MMA (3 products:
// Ah*Bh + Ah*Bl + Al*Bh -> fp32-class accuracy, proven rel_err ~5e-7).
// R16: tap loop unrolled x5 (cross-tap LDSM/MMA overlap) + split accumulator
// chains (hi*hi separate from correction products -> 4 independent HMMA
// chains per warp). Layout identical to proven R15.
// ---------------------------------------------------------------------------
template<int CINP, int CIN, int C0, bool ACT>
__global__ __launch_bounds__(NTHREADS, 3)
void gconv_mma_kernel(const float* __restrict__ in0, long long bs0,
                      const float* __restrict__ in1, long long bs1,
                      const float* __restrict__ W,
                      const float* __restrict__ bias,
                      float* __restrict__ out, int G)
{
    constexpr int NKB16 = CINP / 16;
    constexpr bool HAS8 = (CINP % 16) == 8;
    constexpr int WPI   = NKB16 * 64 + (HAS8 ? 32 : 0);   // B words per (tap,img)
    static_assert(CINP * 2 <= SBB, "row overflow");

    extern __shared__ uint32_t smem[];
    uint32_t* sxh = smem;                        // TROWS * SBW
    uint32_t* sxl = sxh + TROWS * SBW;           // TROWS * SBW
    uint32_t* swB = sxl + TROWS * SBW;           // KW * 2 * WPI
    float*    sb  = (float*)(swB + KW * 2 * WPI);

    const int b   = blockIdx.z;
    const int g   = blockIdx.y;
    const int t0  = blockIdx.x * TT;
    const int tid = threadIdx.x;
    const int warp = tid >> 5, lane = tid & 31;
    const int gid = lane >> 2;                   // 0..7
    const int tig = lane & 3;                    // 0..3
    const int lrow = (lane & 7) + 8 * ((lane >> 3) & 1);
    const int lcol = (lane >> 4) * 16;           // byte offset of ci-half

    // ---- stage split fp16 weights: swB[(tap*2+img)*WPI + slot]
    for (int i = tid; i < KW * 2 * WPI; i += NTHREADS) {
        int slot = i % WPI;
        int r    = i / WPI;
        int img  = r & 1;
        int tap  = r >> 1;
        int ci, oc;
        if (slot < NKB16 * 64) {
            int blk = slot >> 6, s = slot & 63;
            oc = s & 7;
            ci = blk * 16 + (s >> 3) * 2;
        } else {
            int s = slot - NKB16 * 64;
            oc = s & 7;
            ci = NKB16 * 16 + (s >> 3) * 2;
        }
        float w0 = (ci     < CIN) ? W[((long long)(g * 8 + oc) * CIN + ci    ) * KW + tap] : 0.f;
        float w1 = (ci + 1 < CIN) ? W[((long long)(g * 8 + oc) * CIN + ci + 1) * KW + tap] : 0.f;
        uint32_t v;
        if (img == 0) {
            v = packh2(w0, w1);
        } else {
            float h0 = __half2float(__float2half_rn(w0));
            float h1 = __half2float(__float2half_rn(w1));
            v = packh2(w0 - h0, w1 - h1);
        }
        swB[(tap * 2 + img) * WPI + slot] = v;
    }
    if (tid < 8) sb[tid] = bias[g * 8 + tid];

    // ---- stage x transposed + split fp16: xT[t'][ci] ----
    for (int idx = tid; idx < NTQ * (CINP / 4); idx += NTHREADS) {
        int tc = idx % NTQ;                      // lanes consecutive in t-quad
        int cq = idx / NTQ;
        int tg = t0 - 8 + 4 * tc;
        float4 v[4];
#pragma unroll
        for (int j = 0; j < 4; j++) {
            int ci = cq * 4 + j;
            v[j] = make_float4(0.f, 0.f, 0.f, 0.f);
            if (ci < CIN) {
                const float* src;
                if (C0 == CIN || ci < C0)
                    src = in0 + (long long)b * bs0 + (long long)(g * C0 + ci) * TLEN;
                else
                    src = in1 + (long long)b * bs1 + (long long)(g * (CIN - C0) + (ci - C0)) * TLEN;
                if (tg >= 0 && tg <= TLEN - 4) {
                    v[j] = *(const float4*)(src + tg);
                } else {
                    float* p = (float*)&v[j];
#pragma unroll
                    for (int k = 0; k < 4; k++) {
                        int t = tg + k;
                        if (t >= 0 && t < TLEN) p[k] = src[t];
                    }
                }
            }
        }
#pragma unroll
        for (int k = 0; k < 4; k++) {
            float x0 = ((float*)&v[0])[k];
            float x1 = ((float*)&v[1])[k];
            float x2 = ((float*)&v[2])[k];
            float x3 = ((float*)&v[3])[k];
            float h0 = __half2float(__float2half_rn(x0));
            float h1 = __half2float(__float2half_rn(x1));
            float h2 = __half2float(__float2half_rn(x2));
            float h3 = __half2float(__float2half_rn(x3));
            int off = (4 * tc + k) * SBW + cq * 2;
            sxh[off]     = packh2(x0, x1);
            sxh[off + 1] = packh2(x2, x3);
            sxl[off]     = packh2(x0 - h0, x1 - h1);
            sxl[off + 1] = packh2(x2 - h2, x3 - h3);
        }
    }
    __syncthreads();

    // ---- compute: split accumulator chains (a: hi*hi, b: corrections) ----
    float d0a[4] = {0.f, 0.f, 0.f, 0.f};
    float d0b[4] = {0.f, 0.f, 0.f, 0.f};
    float d1a[4] = {0.f, 0.f, 0.f, 0.f};
    float d1b[4] = {0.f, 0.f, 0.f, 0.f};

    uint32_t axh = (uint32_t)__cvta_generic_to_shared(sxh)
                 + (uint32_t)((warp * 32 + 1 + lrow) * SBB + lcol);
    uint32_t axl = axh + (uint32_t)(TROWS * SBB);

#pragma unroll 5
    for (int tap = 0; tap < KW; tap++) {
        const uint32_t* wbh = swB + (tap * 2 + 0) * WPI;
        const uint32_t* wbl = swB + (tap * 2 + 1) * WPI;
        uint32_t roff = (uint32_t)(tap * SBB);

#pragma unroll
        for (int blk = 0; blk < NKB16; blk++) {
            int bidx = blk * 64 + tig * 8 + gid;
            uint32_t bh0 = wbh[bidx], bh1 = wbh[bidx + 32];
            uint32_t bl0 = wbl[bidx], bl1 = wbl[bidx + 32];
            uint32_t coff = roff + (uint32_t)(blk * 32);
            uint32_t toff = coff + (uint32_t)(16 * SBB);

            uint32_t p0, p1, p2, p3, q0, q1, q2, q3;   // tile0 hi / lo
            uint32_t r0, r1, r2, r3, s0, s1, s2, s3;   // tile1 hi / lo
            ldsm_x4(p0, p1, p2, p3, axh + coff);
            ldsm_x4(q0, q1, q2, q3, axl + coff);
            ldsm_x4(r0, r1, r2, r3, axh + toff);
            ldsm_x4(s0, s1, s2, s3, axl + toff);

            mma_f16_k16(d0a, p0, p1, p2, p3, bh0, bh1);   // hi*hi
            mma_f16_k16(d0b, p0, p1, p2, p3, bl0, bl1);   // hi*lo
            mma_f16_k16(d0b, q0, q1, q2, q3, bh0, bh1);   // lo*hi
            mma_f16_k16(d1a, r0, r1, r2, r3, bh0, bh1);
            mma_f16_k16(d1b, r0, r1, r2, r3, bl0, bl1);
            mma_f16_k16(d1b, s0, s1, s2, s3, bh0, bh1);
        }
        if (HAS8) {
            int bidx = NKB16 * 64 + tig * 8 + gid;
            uint32_t bh0 = wbh[bidx];
            uint32_t bl0 = wbl[bidx];
            uint32_t coff = roff + (uint32_t)(NKB16 * 32);
            uint32_t toff = coff + (uint32_t)(16 * SBB);

            uint32_t p0, p1, q0, q1, r0, r1, s0, s1;
            ldsm_x2(p0, p1, axh + coff);
            ldsm_x2(q0, q1, axl + coff);
            ldsm_x2(r0, r1, axh + toff);
            ldsm_x2(s0, s1, axl + toff);

            mma_f16_k8(d0a, p0, p1, bh0);
            mma_f16_k8(d0b, p0, p1, bl0);
            mma_f16_k8(d0b, q0, q1, bh0);
            mma_f16_k8(d1a, r0, r1, bh0);
            mma_f16_k8(d1b, r0, r1, bl0);
            mma_f16_k8(d1b, s0, s1, bh0);
        }
    }

    // ---- epilogue: merge chains, bias + leaky relu (proven D map) ----
    const float bv0 = sb[2 * tig];
    const float bv1 = sb[2 * tig + 1];
    float* obase = out + ((long long)(b * G + g) * 8) * TLEN + t0 + warp * 32;
    float* o0 = obase + (long long)(2 * tig) * TLEN;
    float* o1 = obase + (long long)(2 * tig + 1) * TLEN;

    auto act = [](float v, bool on) { return on ? (v > 0.f ? v : 0.01f * v) : v; };
    o0[gid]      = act(d0a[0] + d0b[0] + bv0, ACT);
    o1[gid]      = act(d0a[1] + d0b[1] + bv1, ACT);
    o0[gid + 8]  = act(d0a[2] + d0b[2] + bv0, ACT);
    o1[gid + 8]  = act(d0a[3] + d0b[3] + bv1, ACT);
    o0[gid + 16] = act(d1a[0] + d1b[0] + bv0, ACT);
    o1[gid + 16] = act(d1a[1] + d1b[1] + bv1, ACT);
    o0[gid + 24] = act(d1a[2] + d1b[2] + bv0, ACT);
    o1[gid + 24] = act(d1a[3] + d1b[3] + bv1, ACT);
}

// ---------------------------------------------------------------------------
// Root: 1x1 conv over 16 channels -> 1 channel (no activation)
// ---------------------------------------------------------------------------
__global__ void root_kernel(const float* __restrict__ h,
                            const float* __restrict__ w,
                            const float* __restrict__ bias,
                            float* __restrict__ out)
{
    int idx = blockIdx.x * blockDim.x + threadIdx.x;
    if (idx >= BATCH * TLEN) return;
    int b = idx / TLEN;
    int t = idx - b * TLEN;
    const float* hp = h + (long long)b * 16 * TLEN + t;
    float s = bias[0];
#pragma unroll
    for (int c = 0; c < 16; c++)
        s = fmaf(__ldg(&w[c]), hp[(long long)c * TLEN], s);
    out[idx] = s;
}

// ---------------------------------------------------------------------------
// Launch
// ---------------------------------------------------------------------------
static inline int wpi(int cinp) { return (cinp / 16) * 64 + ((cinp % 16) / 8) * 32; }
static inline int smem_bytes(int cinp) {
    return (2 * TROWS * SBW + KW * 2 * wpi(cinp) + 8) * 4;
}

extern "C" void kernel_launch(void* const* d_in, const int* in_sizes, int n_in,
                              void* d_out, int out_size)
{
    const float* x      = (const float*)d_in[0];
    const float* W_leaf = (const float*)d_in[1];
    const float* b_leaf = (const float*)d_in[2];
    const float* W_int0 = (const float*)d_in[3];
    const float* b_int0 = (const float*)d_in[4];
    const float* W_br   = (const float*)d_in[5];
    const float* b_br   = (const float*)d_in[6];
    const float* W_int1 = (const float*)d_in[7];
    const float* b_int1 = (const float*)d_in[8];
    const float* W_int2 = (const float*)d_in[9];
    const float* b_int2 = (const float*)d_in[10];
    const float* W_int3 = (const float*)d_in[11];
    const float* b_int3 = (const float*)d_in[12];
    const float* W_int4 = (const float*)d_in[13];
    const float* b_int4 = (const float*)d_in[14];
    const float* W_root = (const float*)d_in[15];
    const float* b_root = (const float*)d_in[16];
    float* out = (float*)d_out;

    float *h1, *h2, *h3, *h4, *h5, *h6, *h7;
    cudaGetSymbolAddress((void**)&h1, g_h1);
    cudaGetSymbolAddress((void**)&h2, g_h2);
    cudaGetSymbolAddress((void**)&h3, g_h3);
    cudaGetSymbolAddress((void**)&h4, g_h4);
    cudaGetSymbolAddress((void**)&h5, g_h5);
    cudaGetSymbolAddress((void**)&h6, g_h6);
    cudaGetSymbolAddress((void**)&h7, g_h7);

    const int TB = TLEN / TT;   // 16 tiles along T
    const long long BSX = (long long)1536 * TLEN;

    const int SM24 = smem_bytes(24);   // leaf: k16 + k8 tail  (~37.5 KB)
    const int SM16 = smem_bytes(16);   // ints: one k16 block (~34 KB)

    cudaFuncSetAttribute(gconv_mma_kernel<24, 20, 20, true>,
                         cudaFuncAttributeMaxDynamicSharedMemorySize, SM24);
    cudaFuncSetAttribute(gconv_mma_kernel<16, 16, 16, true>,
                         cudaFuncAttributeMaxDynamicSharedMemorySize, SM16);
    cudaFuncSetAttribute(gconv_mma_kernel<16, 16, 8, true>,
                         cudaFuncAttributeMaxDynamicSharedMemorySize, SM16);

    // 1. leaf: 64 groups, 20 in/group (padded to 24 = k16 + k8), 8 out/group
    gconv_mma_kernel<24, 20, 20, true><<<dim3(TB, 64, BATCH), NTHREADS, SM24>>>(
        x, BSX, nullptr, 0, W_leaf, b_leaf, h1, 64);

    // 2. int0: 32 groups, 16 in/group (from 512 ch)
    gconv_mma_kernel<16, 16, 16, true><<<dim3(TB, 32, BATCH), NTHREADS, SM16>>>(
        h1, (long long)512 * TLEN, nullptr, 0, W_int0, b_int0, h2, 32);

    // 3. br: 32 groups, in/group = 8 (h2) + 8 (syn = x channels 1280..1535)
    gconv_mma_kernel<16, 16, 8, true><<<dim3(TB, 32, BATCH), NTHREADS, SM16>>>(
        h2, (long long)256 * TLEN,
        x + (long long)1280 * TLEN, BSX,
        W_br, b_br, h3, 32);

    // 4. int1: 16 groups (256 -> 128)
    gconv_mma_kernel<16, 16, 16, true><<<dim3(TB, 16, BATCH), NTHREADS, SM16>>>(
        h3, (long long)256 * TLEN, nullptr, 0, W_int1, b_int1, h4, 16);

    // 5. int2: 8 groups (128 -> 64)
    gconv_mma_kernel<16, 16, 16, true><<<dim3(TB, 8, BATCH), NTHREADS, SM16>>>(
        h4, (long long)128 * TLEN, nullptr, 0, W_int2, b_int2, h5, 8);

    // 6. int3: 4 groups (64 -> 32)
    gconv_mma_kernel<16, 16, 16, true><<<dim3(TB, 4, BATCH), NTHREADS, SM16>>>(
        h5, (long long)64 * TLEN, nullptr, 0, W_int3, b_int3, h6, 4);

    // 7. int4: 2 groups (32 -> 16)
    gconv_mma_kernel<16, 16, 16, true><<<dim3(TB, 2, BATCH), NTHREADS, SM16>>>(
        h6, (long long)32 * TLEN, nullptr, 0, W_int4, b_int4, h7, 2);

    // 8. root: 1x1 conv 16 -> 1
    root_kernel<<<(BATCH * TLEN + 255) / 256, 256>>>(h7, W_root, b_root, out);
}